// round 2
// baseline (speedup 1.0000x reference)
#include <cuda_runtime.h>
#include <math.h>

#define BB 32
#define TT 2048
#define DIN 64
#define HH 1024
#define DOUT 64
#define NSTEPS 60
#define C1 8
#define C2 16
#define C3 32
#define K1 4
#define K2 8
#define K3 16
#define LEN1 2045
#define LEN2 2038
#define LL 2023
#define KT1 1152          /* [ctx1(32) prev(64) h1(1024) pad(32)] */
#define KT23 2160         /* [ctx(32) h_prev(1024) h_self(1024) pad(80)] */
#define KC 18
#define CH1 64            /* KT1/KC */
#define CH23 120          /* KT23/KC */
#define G4 4096

typedef unsigned long long ull;

/* ------------- static device scratch (no runtime allocation) ------------- */
__device__ __align__(16) float d_Wcat1[G4 * KT1];
__device__ __align__(16) float d_Wcat2[G4 * KT23];
__device__ __align__(16) float d_Wcat3[G4 * KT23];
__device__ __align__(16) float d_cbias1[G4];
__device__ __align__(16) float d_cbias2[G4];
__device__ __align__(16) float d_cbias3[G4];
__device__ __align__(16) float d_woutT[HH * DOUT];
__device__ __align__(16) float d_buf1[BB * C1 * LEN1];
__device__ __align__(16) float d_buf2[BB * C2 * LEN2];
__device__ __align__(16) float d_enc[BB * LL * C3];
__device__ __align__(16) float d_gpart[KC * G4 * BB];
__device__ __align__(16) float d_xin1[BB * KT1];
__device__ __align__(16) float d_xin2[BB * KT23];
__device__ __align__(16) float d_xin3[BB * KT23];
__device__ __align__(16) float d_h1[BB * HH];
__device__ __align__(16) float d_c1[BB * HH];
__device__ __align__(16) float d_h2[BB * HH];
__device__ __align__(16) float d_c2[BB * HH];
__device__ __align__(16) float d_h3[BB * HH];
__device__ __align__(16) float d_c3[BB * HH];

/* barrier state: monotonic generation counter -> replay-safe, no reset */
__device__ unsigned bar_count = 0;
__device__ unsigned bar_gen = 0;

/* ---------------------------- helpers ------------------------------------ */
__device__ __forceinline__ ull pack2(float x, float y) {
    ull r;
    asm("mov.b64 %0, {%1, %2};" : "=l"(r) : "f"(x), "f"(y));
    return r;
}
__device__ __forceinline__ void fma2(ull& acc, ull a, ull b) {
    asm("fma.rn.f32x2 %0, %1, %2, %0;" : "+l"(acc) : "l"(a), "l"(b));
}
__device__ __forceinline__ float sigf(float x) { return 1.f / (1.f + expf(-x)); }

__device__ __forceinline__ void gbar(unsigned& genloc, int nblk) {
    __syncthreads();
    if (threadIdx.x == 0) {
        __threadfence();
        unsigned target = genloc + 1;
        unsigned arrived = atomicAdd(&bar_count, 1u);
        if (arrived == (unsigned)(nblk - 1)) {
            *((volatile unsigned*)&bar_count) = 0u;
            __threadfence();
            atomicExch(&bar_gen, target);
        } else {
            while ((int)(*((volatile unsigned*)&bar_gen) - target) < 0) {}
        }
        genloc = target;
    }
    __syncthreads();
}

/* ------------------------ weight concat precompute ----------------------- */
__global__ void wcat_kernel(int which, const float* __restrict__ wih,
                            const float* __restrict__ whh, int kx, int kt) {
    float* dst = which == 0 ? d_Wcat1 : which == 1 ? d_Wcat2 : d_Wcat3;
    size_t total = (size_t)G4 * kt;
    for (size_t idx = (size_t)blockIdx.x * blockDim.x + threadIdx.x; idx < total;
         idx += (size_t)gridDim.x * blockDim.x) {
        int n = (int)(idx / kt), col = (int)(idx % kt);
        float v;
        if (col < kx)
            v = wih[(size_t)n * kx + col];
        else if (col < kx + HH)
            v = whh[(size_t)n * HH + (col - kx)];
        else
            v = 0.f;
        dst[idx] = v;
    }
}

__global__ void misc_kernel(const float* __restrict__ bih1, const float* __restrict__ bhh1,
                            const float* __restrict__ bih2, const float* __restrict__ bhh2,
                            const float* __restrict__ bih3, const float* __restrict__ bhh3,
                            const float* __restrict__ wout) {
    int idx = blockIdx.x * 256 + threadIdx.x;
    if (idx < G4) {
        d_cbias1[idx] = bih1[idx] + bhh1[idx];
        d_cbias2[idx] = bih2[idx] + bhh2[idx];
        d_cbias3[idx] = bih3[idx] + bhh3[idx];
    }
    if (idx < HH * DOUT) {
        int hh = idx / DOUT, d = idx % DOUT;
        d_woutT[idx] = wout[(size_t)d * HH + hh];
    }
}

/* ------------------------------- init ------------------------------------ */
__global__ void init_kernel(const float* __restrict__ x) {
    const int NHC = 6 * BB * HH;
    const int NX1 = BB * KT1;
    const int NX23 = BB * KT23;
    const int TOTAL = NHC + NX1 + 2 * NX23;
    for (int idx = blockIdx.x * blockDim.x + threadIdx.x; idx < TOTAL;
         idx += gridDim.x * blockDim.x) {
        int t = idx;
        if (t < NHC) {
            int which = t / (BB * HH);
            int off = t & (BB * HH - 1);
            float* p = which == 0 ? d_h1 : which == 1 ? d_c1 : which == 2 ? d_h2
                     : which == 3 ? d_c2 : which == 4 ? d_h3 : d_c3;
            p[off] = 0.f;
        } else if (t < NHC + NX1) {
            t -= NHC;
            int b = t / KT1, col = t % KT1;
            float v = 0.f;
            if (col >= 32 && col < 96)
                v = x[((size_t)b * TT + (TT - 1)) * DIN + (col - 32)];
            d_xin1[t] = v;
        } else {
            t -= NHC + NX1;
            if (t < NX23) d_xin2[t] = 0.f;
            else d_xin3[t - NX23] = 0.f;
        }
    }
}

/* ------------------------------ conv stack ------------------------------- */
__global__ void conv1_kernel(const float* __restrict__ x, const float* __restrict__ w,
                             const float* __restrict__ bias) {
    __shared__ float ws[DIN * K1];
    int c = blockIdx.y, b = blockIdx.z, tid = threadIdx.x;
    if (tid < DIN * K1) ws[tid] = w[c * DIN * K1 + tid];
    __syncthreads();
    int t = blockIdx.x * 256 + tid;
    if (t >= LEN1) return;
    const float* xp = x + ((size_t)b * TT + t) * DIN;
    float acc = bias[c];
#pragma unroll
    for (int k = 0; k < K1; k++)
#pragma unroll
        for (int i = 0; i < DIN; i++) acc += xp[k * DIN + i] * ws[i * K1 + k];
    d_buf1[((size_t)b * C1 + c) * LEN1 + t] = fmaxf(acc, 0.f);
}

__global__ void conv2_kernel(const float* __restrict__ w, const float* __restrict__ bias) {
    __shared__ float ws[C1 * K2];
    int c = blockIdx.y, b = blockIdx.z, tid = threadIdx.x;
    if (tid < C1 * K2) ws[tid] = w[c * C1 * K2 + tid];
    __syncthreads();
    int t = blockIdx.x * 256 + tid;
    if (t >= LEN2) return;
    float acc = bias[c];
    const float* ip = d_buf1 + (size_t)b * C1 * LEN1;
#pragma unroll
    for (int i = 0; i < C1; i++) {
        const float* row = ip + i * LEN1 + t;
#pragma unroll
        for (int k = 0; k < K2; k++) acc += row[k] * ws[i * K2 + k];
    }
    d_buf2[((size_t)b * C2 + c) * LEN2 + t] = fmaxf(acc, 0.f);
}

__global__ void conv3_kernel(const float* __restrict__ w, const float* __restrict__ bias) {
    __shared__ float ws[C3 * 257];
    int b = blockIdx.y, tid = threadIdx.x;
    for (int i = tid; i < C3 * C2 * K3; i += 256) {
        int c = i / (C2 * K3), r = i % (C2 * K3);
        ws[c * 257 + r] = w[i];
    }
    __syncthreads();
    int c = tid & 31, tl = tid >> 5;
    int t = blockIdx.x * 8 + tl;
    if (t >= LL) return;
    float acc = bias[c];
    const float* ip = d_buf2 + (size_t)b * C2 * LEN2;
    const float* wp = ws + c * 257;
#pragma unroll
    for (int i = 0; i < C2; i++) {
        const float* row = ip + i * LEN2 + t;
#pragma unroll
        for (int k = 0; k < K3; k++) acc += row[k] * wp[i * K3 + k];
    }
    d_enc[((size_t)b * LL + t) * C3 + c] = fmaxf(acc, 0.f);
}

/* ====================== persistent loop kernel =========================== */

union SmemPool {
    float xs[CH23 * 34];                               /* mm x-tile (16320B)  */
    struct {
        float sc[LL];
        float red[256];
        float hp[32];
        float stot;
    } a;                                               /* attention scratch   */
};

/* ---- attention for (j, b): ctx_j[b] -> xin_j[b, 0:32] ---- */
__device__ void att_work(SmemPool& sp, int j, int b, const float* __restrict__ wa) {
    int tid = threadIdx.x;
    const float* hb = (j == 0 ? d_h1 : j == 1 ? d_h2 : d_h3) + b * HH;
    int d = tid & 31, seg = tid >> 5;
    float part = 0.f;
    for (int hh = seg * 128; hh < seg * 128 + 128; hh++)
        part += __ldcg(&hb[hh]) * wa[hh * 32 + d];
    sp.a.red[tid] = part;
    __syncthreads();
    if (tid < 32) {
        float sm = 0.f;
#pragma unroll
        for (int q = 0; q < 8; q++) sm += sp.a.red[q * 32 + tid];
        sp.a.hp[tid] = sm;
    }
    __syncthreads();
    const float* eb = d_enc + (size_t)b * LL * C3;
    float mx = -1e30f;
    for (int l = tid; l < LL; l += 256) {
        const float4* r = (const float4*)(eb + l * 32);
        float acc = 0.f;
#pragma unroll
        for (int q = 0; q < 8; q++) {
            float4 v = r[q];
            acc += v.x * sp.a.hp[4 * q] + v.y * sp.a.hp[4 * q + 1] +
                   v.z * sp.a.hp[4 * q + 2] + v.w * sp.a.hp[4 * q + 3];
        }
        sp.a.sc[l] = acc;
        mx = fmaxf(mx, acc);
    }
    sp.a.red[tid] = mx;
    __syncthreads();
    for (int st = 128; st > 0; st >>= 1) {
        if (tid < st) sp.a.red[tid] = fmaxf(sp.a.red[tid], sp.a.red[tid + st]);
        __syncthreads();
    }
    mx = sp.a.red[0];
    __syncthreads();
    float ls = 0.f;
    for (int l = tid; l < LL; l += 256) {
        float e = expf(sp.a.sc[l] - mx);
        sp.a.sc[l] = e;
        ls += e;
    }
    sp.a.red[tid] = ls;
    __syncthreads();
    for (int st = 128; st > 0; st >>= 1) {
        if (tid < st) sp.a.red[tid] += sp.a.red[tid + st];
        __syncthreads();
    }
    if (tid == 0) sp.a.stot = sp.a.red[0];
    __syncthreads();
    float inv = 1.f / sp.a.stot;
    int g2 = tid >> 5;
    d = tid & 31;
    float ca = 0.f;
    for (int l = g2; l < LL; l += 8) ca += sp.a.sc[l] * eb[l * 32 + d];
    __syncthreads();
    sp.a.red[tid] = ca;
    __syncthreads();
    if (tid < 32) {
        float sm = 0.f;
#pragma unroll
        for (int q = 0; q < 8; q++) sm += sp.a.red[q * 32 + tid];
        float* xin = j == 0 ? d_xin1 : j == 1 ? d_xin2 : d_xin3;
        int kt = j == 0 ? KT1 : KT23;
        xin[b * kt + tid] = sm * inv;
    }
}

/* ---- y for batch b: y_{s-1} = h3 @ woutT + bout ---- */
__device__ void y_work(SmemPool& sp, int b, int s, const float* __restrict__ bout,
                       float* __restrict__ out, bool write_xin) {
    if (s == 0) return;
    int tid = threadIdx.x;
    int d = tid & 63, seg = tid >> 6;
    const float* hb = d_h3 + b * HH;
    float part = 0.f;
    for (int hh = seg * 256; hh < seg * 256 + 256; hh++)
        part += __ldcg(&hb[hh]) * d_woutT[hh * DOUT + d];
    sp.a.red[tid] = part;
    __syncthreads();
    if (tid < 64) {
        float y = bout[tid];
#pragma unroll
        for (int q = 0; q < 4; q++) y += sp.a.red[q * 64 + tid];
        out[((size_t)b * NSTEPS + (s - 1)) * DOUT + tid] = y;
        if (write_xin) d_xin1[b * KT1 + 32 + tid] = y;
    }
}

/* ---- LSTM gate GEMM chunk: vb in [0,144), f32x2 over batch pairs ---- */
__device__ void mm_work(SmemPool& sp, int vb, const float* __restrict__ W,
                        const float* __restrict__ X, int KT, int KSUB) {
    int tid = threadIdx.x;
    int kch = vb >> 3;
    int k0 = kch * KSUB;
    int n0 = (vb & 7) * 512 + (tid >> 2) * 8;
    int b0 = (tid & 3) * 8;

    for (int idx = tid; idx < KSUB * BB; idx += 256) {
        int b = idx / KSUB, k = idx % KSUB;
        sp.xs[k * 34 + b] = __ldcg(&X[b * KT + k0 + k]);
    }
    __syncthreads();

    ull acc[8][4];
#pragma unroll
    for (int i = 0; i < 8; i++)
#pragma unroll
        for (int p = 0; p < 4; p++) acc[i][p] = 0ULL;

    const float* Wp = W + (size_t)n0 * KT + k0;
    for (int kk = 0; kk < KSUB; kk += 4) {
        float4 w4[8];
#pragma unroll
        for (int i = 0; i < 8; i++) w4[i] = *(const float4*)(Wp + (size_t)i * KT + kk);
#pragma unroll
        for (int q = 0; q < 4; q++) {
            ull xp[4];
            const float* xr = sp.xs + (kk + q) * 34 + b0;
#pragma unroll
            for (int p = 0; p < 4; p++) xp[p] = *(const ull*)(xr + 2 * p);
#pragma unroll
            for (int i = 0; i < 8; i++) {
                float wv = q == 0 ? w4[i].x : q == 1 ? w4[i].y : q == 2 ? w4[i].z : w4[i].w;
                ull wp2 = pack2(wv, wv);
#pragma unroll
                for (int p = 0; p < 4; p++) fma2(acc[i][p], wp2, xp[p]);
            }
        }
    }

    float* gpo = d_gpart + (size_t)kch * G4 * BB;
#pragma unroll
    for (int i = 0; i < 8; i++) {
        float* row = gpo + (size_t)(n0 + i) * BB + b0;
#pragma unroll
        for (int p = 0; p < 4; p++) *(ull*)(row + 2 * p) = acc[i][p];
    }
}

/* ---- epilogue chunk: vb in [0,128) ---- */
__device__ void epi_work(int vb, int cell) {
    const float* cb = cell == 0 ? d_cbias1 : cell == 1 ? d_cbias2 : d_cbias3;
    float* cst = cell == 0 ? d_c1 : cell == 1 ? d_c2 : d_c3;
    float* hst = cell == 0 ? d_h1 : cell == 1 ? d_h2 : d_h3;
    int idx = vb * 256 + threadIdx.x;
    int j = idx >> 5, b = idx & 31;
    float g[4];
#pragma unroll
    for (int gt = 0; gt < 4; gt++) {
        float s = cb[gt * HH + j];
        const float* gp = d_gpart + (size_t)(gt * HH + j) * BB + b;
#pragma unroll
        for (int kc = 0; kc < KC; kc++) s += __ldcg(&gp[(size_t)kc * G4 * BB]);
        g[gt] = s;
    }
    float c = sigf(g[1]) * __ldcg(&cst[b * HH + j]) + sigf(g[0]) * tanhf(g[2]);
    float h = sigf(g[3]) * tanhf(c);
    cst[b * HH + j] = c;
    hst[b * HH + j] = h;
    if (cell == 0) {
        d_xin2[b * KT23 + 32 + j] = h;
        d_xin1[b * KT1 + 96 + j] = h;
    } else if (cell == 1) {
        d_xin3[b * KT23 + 32 + j] = h;
        d_xin2[b * KT23 + 1056 + j] = h;
    } else {
        d_xin3[b * KT23 + 1056 + j] = h;
    }
}

__global__ __launch_bounds__(256) void loop_kernel(
    const float* __restrict__ wa1, const float* __restrict__ wa2,
    const float* __restrict__ wa3, const float* __restrict__ bout,
    float* __restrict__ out, int nblk) {
    __shared__ SmemPool sp;
    int blk = blockIdx.x;
    unsigned genloc = 0;
    if (threadIdx.x == 0) genloc = *((volatile unsigned*)&bar_gen);

    for (int s = 0; s < NSTEPS; s++) {
        /* phase A: 3x attention (vb<96) + y of prev step (vb in 96..127) */
        for (int vb = blk; vb < 128; vb += nblk) {
            __syncthreads();
            if (vb < 96) {
                int j = vb >> 5, b = vb & 31;
                att_work(sp, j, b, j == 0 ? wa1 : j == 1 ? wa2 : wa3);
            } else {
                y_work(sp, vb - 96, s, bout, out, true);
            }
        }
        gbar(genloc, nblk);

        /* cell 1 */
        for (int vb = blk; vb < 144; vb += nblk) {
            __syncthreads();
            mm_work(sp, vb, d_Wcat1, d_xin1, KT1, CH1);
        }
        gbar(genloc, nblk);
        for (int vb = blk; vb < 128; vb += nblk) epi_work(vb, 0);
        gbar(genloc, nblk);

        /* cell 2 */
        for (int vb = blk; vb < 144; vb += nblk) {
            __syncthreads();
            mm_work(sp, vb, d_Wcat2, d_xin2, KT23, CH23);
        }
        gbar(genloc, nblk);
        for (int vb = blk; vb < 128; vb += nblk) epi_work(vb, 1);
        gbar(genloc, nblk);

        /* cell 3 */
        for (int vb = blk; vb < 144; vb += nblk) {
            __syncthreads();
            mm_work(sp, vb, d_Wcat3, d_xin3, KT23, CH23);
        }
        gbar(genloc, nblk);
        for (int vb = blk; vb < 128; vb += nblk) epi_work(vb, 2);
        gbar(genloc, nblk);
    }

    /* final y (step 59 output) */
    for (int vb = blk; vb < 32; vb += nblk) {
        __syncthreads();
        y_work(sp, vb, NSTEPS, bout, out, false);
    }
}

/* ------------------------------ launcher --------------------------------- */
extern "C" void kernel_launch(void* const* d_in, const int* in_sizes, int n_in,
                              void* d_out, int out_size) {
    (void)in_sizes; (void)n_in; (void)out_size;
    const float* x    = (const float*)d_in[0];
    const float* w_c1 = (const float*)d_in[1];
    const float* b_c1 = (const float*)d_in[2];
    const float* w_c2 = (const float*)d_in[3];
    const float* b_c2 = (const float*)d_in[4];
    const float* w_c3 = (const float*)d_in[5];
    const float* b_c3 = (const float*)d_in[6];
    const float* w_a1 = (const float*)d_in[7];
    const float* w_a2 = (const float*)d_in[9];
    const float* w_a3 = (const float*)d_in[11];
    const float* wih1 = (const float*)d_in[13];
    const float* whh1 = (const float*)d_in[14];
    const float* bih1 = (const float*)d_in[15];
    const float* bhh1 = (const float*)d_in[16];
    const float* wih2 = (const float*)d_in[17];
    const float* whh2 = (const float*)d_in[18];
    const float* bih2 = (const float*)d_in[19];
    const float* bhh2 = (const float*)d_in[20];
    const float* wih3 = (const float*)d_in[21];
    const float* whh3 = (const float*)d_in[22];
    const float* bih3 = (const float*)d_in[23];
    const float* bhh3 = (const float*)d_in[24];
    const float* wout = (const float*)d_in[25];
    const float* bout = (const float*)d_in[26];
    float* out = (float*)d_out;

    static int nblk = 0;
    if (nblk == 0) {
        int sm = 0;
        cudaDeviceGetAttribute(&sm, cudaDevAttrMultiProcessorCount, 0);
        nblk = sm < 148 ? sm : 148;
        if (nblk < 1) nblk = 1;
    }

    wcat_kernel<<<2048, 256>>>(0, wih1, whh1, C3 + DIN, KT1);
    wcat_kernel<<<2048, 256>>>(1, wih2, whh2, C3 + HH, KT23);
    wcat_kernel<<<2048, 256>>>(2, wih3, whh3, C3 + HH, KT23);
    misc_kernel<<<256, 256>>>(bih1, bhh1, bih2, bhh2, bih3, bhh3, wout);
    init_kernel<<<1452, 256>>>(x);
    conv1_kernel<<<dim3(8, C1, BB), 256>>>(x, w_c1, b_c1);
    conv2_kernel<<<dim3(8, C2, BB), 256>>>(w_c2, b_c2);
    conv3_kernel<<<dim3(253, BB), 256>>>(w_c3, b_c3);

    loop_kernel<<<nblk, 256>>>(w_a1, w_a2, w_a3, bout, out, nblk);
}